// round 13
// baseline (speedup 1.0000x reference)
#include <cuda_runtime.h>

#define NBATCH 2048
#define NT     48
#define NC     35
#define NE     19
#define NH     128
#define RROWS  16
#define NTHR   512
#define NBLK   128
#define NPAIR  665
// G GEMM: 512 gate-rows x 200 k (70 cc2 + 2 pad + 128 h), chunks of 20 k
#define GKC    20
#define GCH    10
#define GRCH   (NH * 4 * GKC)     // 10240 raw floats per chunk
#define GSTG   (NH * 84)          // 10752 staged floats (row pad 80->84)
// E GEMM: 672 pairs x 72 k, k-major chunks of 12 k
#define EKC    12
#define ECH    6
#define ERCH   (672 * EKC)        // 8064 floats per chunk [kk][672]

typedef unsigned long long u64;

// ---------------- prepared weights (device scratch) ----------------
__device__ float PW_G[GCH * GRCH];    // [ch][u(128)][gate(4)][kk(20)]
__device__ float PW_E[ECH * ERCH];    // [ch][kk(12)][pair(672)]  (k-major!)
__device__ float PW_FRd[NC * NC];
__device__ float PB_Gd[NH * 4];
__device__ float PDXd[NC];
__device__ float g_blk[NBLK * NT * 5];
__device__ int   g_done;

// ---------------- smem layout (floats) ----------------
#define O_ACT  0            // [200][16]: cc2(70)+pad(2)+h(128), paired rows
#define O_CT   3200         // [128][17]
#define O_DTP  5376         // [35][16]
#define O_XM   5936         // [35][17] x (xt,mt)
#define O_XZ   7128         // [35][17] x (xh, zh-xh)
#define O_XCP  8320         // [35][16]
#define O_CATD 8880         // [72][32]: (gamma|mt) duplicated (a,a)
#define O_TPT  11184        // [672][17] (+8 pad)
#define O_WDH  22616        // 128*35
#define O_WHR  27096        // 35*128
#define O_WFR  31576        // 35*35 (+pad)
#define O_BIA  32808        // 1472
#define O_SRED 34280        // 80
#define O_WB   34360        // 2 * 10752
#define SMEM_FLOATS (O_WB + 2 * GSTG)   // 55864 floats = 223456 B

#define B_BDH 0
#define B_BHR 128
#define B_BFR 168
#define B_BDX 208
#define B_PDX 248
#define B_BCB 288
#define B_PBG 960

// ---------------- helpers ----------------
static __device__ __forceinline__ u64 bcast2(float w) {
    u64 r; asm("mov.b64 %0, {%1, %1};" : "=l"(r) : "f"(w)); return r;
}
static __device__ __forceinline__ void fma2(u64& acc, u64 a, u64 b) {
    asm("fma.rn.f32x2 %0, %1, %2, %0;" : "+l"(acc) : "l"(a), "l"(b));
}
static __device__ __forceinline__ float2 unpack2(u64 v) {
    float2 f; asm("mov.b64 {%0, %1}, %2;" : "=f"(f.x), "=f"(f.y) : "l"(v)); return f;
}
static __device__ __forceinline__ float sigmoidf_(float v) {
    return 1.0f / (1.0f + __expf(-v));
}
static __device__ __forceinline__ float ftanh_(float v) {
    return 1.0f - __fdividef(2.0f, __expf(2.0f * v) + 1.0f);
}
static __device__ __forceinline__ float getc4(float4 v, int kk) {
    return (kk == 0) ? v.x : (kk == 1) ? v.y : (kk == 2) ? v.z : v.w;
}

// ---------------- prep ----------------
__global__ void brits_prep(const float* __restrict__ w_fr,
                           const float* __restrict__ w_comb,
                           const float* __restrict__ w_ih,
                           const float* __restrict__ w_hh,
                           const float* __restrict__ b_ih,
                           const float* __restrict__ b_hh,
                           const float* __restrict__ w_dx)
{
    int i0 = blockIdx.x * blockDim.x + threadIdx.x;
    int n = gridDim.x * blockDim.x;
    if (i0 == 0) g_done = 0;
    for (int i = i0; i < GCH * GRCH; i += n) {
        int c = i / GRCH, rem = i - c * GRCH;
        int u = rem / 80, rem2 = rem - u * 80;
        int j = rem2 / GKC, kk = rem2 - j * GKC;
        int k = c * GKC + kk;
        float v = 0.0f;
        if (k < 70)       v = w_ih[(j * NH + u) * 70 + k];
        else if (k >= 72) v = w_hh[(j * NH + u) * NH + (k - 72)];
        PW_G[i] = v;
    }
    for (int i = i0; i < ECH * ERCH; i += n) {
        int c = i / ERCH, rem = i - c * ERCH;
        int kk = rem / 672, p = rem - kk * 672;
        int k = c * EKC + kk;
        PW_E[i] = (p < NPAIR && k < 70) ? w_comb[p * 70 + k] : 0.0f;
    }
    for (int i = i0; i < NC * NC; i += n) {
        int r = i / NC, c = i - r * NC;
        PW_FRd[i] = (r == c) ? 0.0f : w_fr[i];
    }
    for (int i = i0; i < NH * 4; i += n) {
        int u = i >> 2, j = i & 3;
        PB_Gd[i] = b_ih[j * NH + u] + b_hh[j * NH + u];
    }
    for (int i = i0; i < NC; i += n) PDXd[i] = w_dx[i * NC + i];
}

// ---------------- main (+fused finalize) ----------------
__global__ __launch_bounds__(NTHR, 1)
void brits_main(const float* __restrict__ x, const float* __restrict__ mask,
                const float* __restrict__ delta,
                const float* __restrict__ w_dh, const float* __restrict__ b_dh,
                const float* __restrict__ b_dx,
                const float* __restrict__ w_hr, const float* __restrict__ b_hr,
                const float* __restrict__ b_fr,
                const float* __restrict__ b_comb,
                float* __restrict__ out_loss,
                float* __restrict__ out_imp, float* __restrict__ out_ens)
{
    extern __shared__ float sm[];
    float* sACT = sm + O_ACT;
    float* sCT  = sm + O_CT;
    float* sDTP = sm + O_DTP;
    float* sXM  = sm + O_XM;
    float* sXZ  = sm + O_XZ;
    float* sXCP = sm + O_XCP;
    float* sCAD = sm + O_CATD;
    float* sTPT = sm + O_TPT;
    float* sWDH = sm + O_WDH;
    float* sWHR = sm + O_WHR;
    float* sWFR = sm + O_WFR;
    float* sBIA = sm + O_BIA;
    float* sRED = sm + O_SRED;
    float* sWB  = sm + O_WB;

    const int tid  = threadIdx.x;
    const int lane = tid & 31;
    const int wrp  = tid >> 5;
    const int rowBase = blockIdx.x * RROWS;

    // one-time resident weights/biases + state init
    for (int i = tid; i < NH * NC; i += NTHR) sWDH[i] = w_dh[i];
    for (int i = tid; i < NC * NH; i += NTHR) sWHR[i] = w_hr[i];
    for (int i = tid; i < NC * NC; i += NTHR) sWFR[i] = PW_FRd[i];
    for (int i = tid; i < NH; i += NTHR) sBIA[B_BDH + i] = b_dh[i];
    for (int i = tid; i < NC; i += NTHR) {
        sBIA[B_BHR + i] = b_hr[i];
        sBIA[B_BFR + i] = b_fr[i];
        sBIA[B_BDX + i] = b_dx[i];
        sBIA[B_PDX + i] = PDXd[i];
    }
    for (int i = tid; i < NPAIR; i += NTHR) sBIA[B_BCB + i] = b_comb[i];
    for (int i = tid; i < NH * 4; i += NTHR) sBIA[B_PBG + i] = PB_Gd[i];
    // zero: h region + pad rows 70,71 of sACT; cell state; catDup pad rows
    for (int i = tid; i < 130 * 16; i += NTHR) sACT[70 * 16 + i] = 0.f;
    for (int i = tid; i < NH * 17; i += NTHR) sCT[i] = 0.f;
    for (int i = tid; i < 64; i += NTHR) sCAD[70 * 32 + i] = 0.f;
    __syncthreads();

    const int pgrp = tid >> 2;          // E pair-group (6 pairs), valid < 112
    const int r0e  = (tid & 3) * 4;
    const int uG   = tid >> 2;          // G unit
    const int r0g  = (tid & 3) * 4;

    // staged-copy destinations for G (row pad 80->84)
    int gDst[5];
    #pragma unroll
    for (int i = 0; i < 5; ++i) {
        int f = tid + i * NTHR;         // float4 index, 0..2559
        int u = f / 20, rem = f - u * 20;
        gDst[i] = u * 84 + rem * 4;
    }
    const float4* gsrc4 = reinterpret_cast<const float4*>(PW_G);
    const float4* esrc4 = reinterpret_cast<const float4*>(PW_E);

    float hnew[4];                      // register-carried h across steps
    bool  have_h = false;

    for (int t = 0; t < NT; ++t) {
        float lm = 0.f, l1 = 0.f, l2 = 0.f, lq = 0.f, l4 = 0.f;

        // ---- store register-carried h from previous step ----
        if (have_h) {
            float4 hv = make_float4(hnew[0], hnew[1], hnew[2], hnew[3]);
            *reinterpret_cast<float4*>(&sACT[(72 + uG) * 16 + r0g]) = hv;
        }

        // ---- A: transposed loads ----
        for (int i = tid; i < RROWS * NC; i += NTHR) {
            int r = i / NC, c = i - r * NC;
            size_t gi = ((size_t)(rowBase + r) * NT + t) * NC + c;
            float xv = x[gi], mv = mask[gi], dv = delta[gi];
            sDTP[c * 16 + r] = dv;
            sXM[(c * 17 + r) * 2 + 0] = xv;
            sXM[(c * 17 + r) * 2 + 1] = mv;
            *reinterpret_cast<float2*>(&sCAD[(NC + c) * 32 + r * 2]) =
                make_float2(mv, mv);
            lm += mv;
        }
        __syncthreads();   // A done; h stores visible for B2/C

        // ---- B1: gamma_x -> catDup (duplicated) ----
        for (int i = tid; i < NC * 16; i += NTHR) {
            int c = i >> 4, r = i & 15;
            float gx = __expf(-fmaxf(sDTP[c * 16 + r] * sBIA[B_PDX + c]
                                     + sBIA[B_BDX + c], 0.f));
            *reinterpret_cast<float2*>(&sCAD[c * 32 + r * 2]) = make_float2(gx, gx);
        }
        // ---- B2: gamma_h decay of h in place ----
        for (int task = tid; task < NH * 8; task += NTHR) {
            int h = task >> 3, rg = task & 7, r0 = rg * 2;
            u64 a0 = 0ull, a1 = 0ull;
            const float* wr = sWDH + h * NC;
            #pragma unroll
            for (int k = 0; k < NC; ++k) {
                u64 d = *reinterpret_cast<const u64*>(&sDTP[k * 16 + r0]);
                if (k & 1) fma2(a1, d, bcast2(wr[k]));
                else       fma2(a0, d, bcast2(wr[k]));
            }
            float2 s0 = unpack2(a0), s1 = unpack2(a1);
            float bb = sBIA[B_BDH + h];
            sACT[(72 + h) * 16 + r0 + 0] *= __expf(-fmaxf(s0.x + s1.x + bb, 0.f));
            sACT[(72 + h) * 16 + r0 + 1] *= __expf(-fmaxf(s0.y + s1.y + bb, 0.f));
        }
        __syncthreads();

        // ---- C: x_h ----
        if (tid < NC * 8) {
            int c = tid >> 3, rg = tid & 7, r0 = rg * 2;
            u64 a0 = 0ull, a1 = 0ull;
            const float* wr = sWHR + c * NH;
            #pragma unroll 4
            for (int k0 = 0; k0 < NH; k0 += 4) {
                float4 w = *reinterpret_cast<const float4*>(wr + k0);
                u64 h0 = *reinterpret_cast<const u64*>(&sACT[(72 + k0 + 0) * 16 + r0]);
                u64 h1 = *reinterpret_cast<const u64*>(&sACT[(72 + k0 + 1) * 16 + r0]);
                u64 h2 = *reinterpret_cast<const u64*>(&sACT[(72 + k0 + 2) * 16 + r0]);
                u64 h3 = *reinterpret_cast<const u64*>(&sACT[(72 + k0 + 3) * 16 + r0]);
                fma2(a0, h0, bcast2(w.x)); fma2(a1, h1, bcast2(w.y));
                fma2(a0, h2, bcast2(w.z)); fma2(a1, h3, bcast2(w.w));
            }
            float2 s0 = unpack2(a0), s1 = unpack2(a1);
            float bb = sBIA[B_BHR + c];
            float xh[2] = {s0.x + s1.x + bb, s0.y + s1.y + bb};
            #pragma unroll
            for (int rr = 0; rr < 2; ++rr) {
                int r = r0 + rr;
                sXZ[(c * 17 + r) * 2 + 0] = xh[rr];
                float xt = sXM[(c * 17 + r) * 2 + 0];
                float mt = sXM[(c * 17 + r) * 2 + 1];
                l1 += fabsf(xt - xh[rr]) * mt;
                sXCP[c * 16 + r] = mt * xt + (1.f - mt) * xh[rr];
            }
        }
        __syncthreads();

        // ---- E chunk-0 prefetch (hidden under D) ----
        float4 epre[4];
        #pragma unroll
        for (int i = 0; i < 4; ++i)
            if (tid + i * NTHR < ERCH / 4) epre[i] = esrc4[tid + i * NTHR];

        // ---- D: z_h ----
        if (tid < NC * 8) {
            int c = tid >> 3, rg = tid & 7, r0 = rg * 2;
            u64 a0 = 0ull, a1 = 0ull;
            const float* wr = sWFR + c * NC;
            #pragma unroll
            for (int k = 0; k < NC; ++k) {
                u64 xp = *reinterpret_cast<const u64*>(&sXCP[k * 16 + r0]);
                if (k & 1) fma2(a1, xp, bcast2(wr[k]));
                else       fma2(a0, xp, bcast2(wr[k]));
            }
            float2 s0 = unpack2(a0), s1 = unpack2(a1);
            float bb = sBIA[B_BFR + c];
            #pragma unroll
            for (int rr = 0; rr < 2; ++rr) {
                int r = r0 + rr;
                float z = ((rr == 0) ? (s0.x + s1.x) : (s0.y + s1.y)) + bb;
                float xh = sXZ[(c * 17 + r) * 2 + 0];
                sXZ[(c * 17 + r) * 2 + 1] = z - xh;
                float xt = sXM[(c * 17 + r) * 2 + 0];
                float mt = sXM[(c * 17 + r) * 2 + 1];
                l2 += fabsf(xt - z) * mt;
            }
        }
        __syncthreads();

        // ---- E: alpha GEMM, k-major packed weights, dup activations ----
        {
            u64 acc[4][3];   // [row][pair-pair]
            #pragma unroll
            for (int rr = 0; rr < 4; ++rr)
                #pragma unroll
                for (int jp = 0; jp < 3; ++jp) acc[rr][jp] = 0ull;
            for (int ch = 0; ch < ECH; ++ch) {
                float* wb = sWB + (ch & 1) * GSTG;
                float4* wb4 = reinterpret_cast<float4*>(wb);
                #pragma unroll
                for (int i = 0; i < 4; ++i)
                    if (tid + i * NTHR < ERCH / 4) wb4[tid + i * NTHR] = epre[i];
                if (ch + 1 < ECH) {
                    #pragma unroll
                    for (int i = 0; i < 4; ++i)
                        if (tid + i * NTHR < ERCH / 4)
                            epre[i] = esrc4[(ch + 1) * (ERCH / 4) + tid + i * NTHR];
                }
                __syncthreads();
                if (tid < 448) {
                    int kbase = ch * EKC;
                    #pragma unroll
                    for (int kk = 0; kk < EKC; ++kk) {
                        const float* actk = &sCAD[(kbase + kk) * 32];
                        u64 a0 = *reinterpret_cast<const u64*>(actk + (r0e + 0) * 2);
                        u64 a1 = *reinterpret_cast<const u64*>(actk + (r0e + 1) * 2);
                        u64 a2 = *reinterpret_cast<const u64*>(actk + (r0e + 2) * 2);
                        u64 a3 = *reinterpret_cast<const u64*>(actk + (r0e + 3) * 2);
                        const float* wr = wb + kk * 672 + pgrp * 6;
                        u64 w0 = *reinterpret_cast<const u64*>(wr + 0);
                        u64 w1 = *reinterpret_cast<const u64*>(wr + 2);
                        u64 w2 = *reinterpret_cast<const u64*>(wr + 4);
                        fma2(acc[0][0], a0, w0); fma2(acc[0][1], a0, w1); fma2(acc[0][2], a0, w2);
                        fma2(acc[1][0], a1, w0); fma2(acc[1][1], a1, w1); fma2(acc[1][2], a1, w2);
                        fma2(acc[2][0], a2, w0); fma2(acc[2][1], a2, w1); fma2(acc[2][2], a2, w2);
                        fma2(acc[3][0], a3, w0); fma2(acc[3][1], a3, w1); fma2(acc[3][2], a3, w2);
                    }
                }
            }
            // epilogue
            if (tid < 448) {
                #pragma unroll
                for (int jp = 0; jp < 3; ++jp) {
                    #pragma unroll
                    for (int side = 0; side < 2; ++side) {
                        int p = pgrp * 6 + jp * 2 + side;
                        if (p < NPAIR) {
                            int n = p / NC, c = p - n * NC;
                            float bc = sBIA[B_BCB + p];
                            float qn = (float)(n + 1) * 0.05f;
                            #pragma unroll
                            for (int rr = 0; rr < 4; ++rr) {
                                float2 av = unpack2(acc[rr][jp]);
                                float alpha = ((side == 0) ? av.x : av.y) + bc;
                                int r = r0e + rr;
                                float xh  = sXZ[(c * 17 + r) * 2 + 0];
                                float dzh = sXZ[(c * 17 + r) * 2 + 1];
                                float tp = xh + alpha * dzh;
                                float xt = sXM[(c * 17 + r) * 2 + 0];
                                float mt = sXM[(c * 17 + r) * 2 + 1];
                                float wq = (xt <= tp) ? (1.f - qn) : qn;
                                lq += fabsf(tp - xt) * mt * wq;
                                sTPT[p * 17 + r] = tp;
                            }
                        }
                    }
                }
            }
        }
        __syncthreads();

        // ---- G chunk-0 prefetch (hidden under F) ----
        float4 gpre[5];
        #pragma unroll
        for (int i = 0; i < 5; ++i)
            gpre[i] = gsrc4[tid + i * NTHR];

        // ---- F: ensemble mean, imp out, cc2 into sACT ----
        for (int i = tid; i < NC * 16; i += NTHR) {
            int c = i >> 4, r = i & 15;
            float s = 0.f;
            #pragma unroll
            for (int n = 0; n < NE; ++n) s += sTPT[(n * NC + c) * 17 + r];
            float mean = s * (1.0f / (float)NE);
            float xt = sXM[(c * 17 + r) * 2 + 0];
            float mt = sXM[(c * 17 + r) * 2 + 1];
            l4 += fabsf(xt - mean) * mt;
            float cc = mt * xt + (1.f - mt) * mean;
            out_imp[((size_t)(rowBase + r) * NT + t) * NC + c] = cc;
            sACT[c * 16 + r] = cc;
            sACT[(NC + c) * 16 + r] = mt;
        }
        // ---- ens writes ----
        for (int i = tid; i < RROWS * NPAIR; i += NTHR) {
            int r = i / NPAIR, pn = i - r * NPAIR;
            int n = pn / NC, c = pn - n * NC;
            float tp = sTPT[pn * 17 + r];
            float xt = sXM[(c * 17 + r) * 2 + 0];
            float mt = sXM[(c * 17 + r) * 2 + 1];
            out_ens[(((size_t)(rowBase + r) * NE + n) * NT + t) * NC + c]
                = mt * xt + (1.f - mt) * tp;
        }
        // ---- loss reduce ----
        {
            float v0 = lm, v1 = l1, v2 = l2, v3 = lq, v4 = l4;
            #pragma unroll
            for (int o = 16; o > 0; o >>= 1) {
                v0 += __shfl_down_sync(0xffffffffu, v0, o);
                v1 += __shfl_down_sync(0xffffffffu, v1, o);
                v2 += __shfl_down_sync(0xffffffffu, v2, o);
                v3 += __shfl_down_sync(0xffffffffu, v3, o);
                v4 += __shfl_down_sync(0xffffffffu, v4, o);
            }
            if (lane == 0) {
                sRED[wrp * 5 + 0] = v0; sRED[wrp * 5 + 1] = v1;
                sRED[wrp * 5 + 2] = v2; sRED[wrp * 5 + 3] = v3;
                sRED[wrp * 5 + 4] = v4;
            }
        }
        __syncthreads();
        if (tid == 0) {
            float s0 = 0.f, s1 = 0.f, s2 = 0.f, s3 = 0.f, s4 = 0.f;
            for (int w = 0; w < NTHR / 32; ++w) {
                s0 += sRED[w * 5 + 0]; s1 += sRED[w * 5 + 1];
                s2 += sRED[w * 5 + 2]; s3 += sRED[w * 5 + 3];
                s4 += sRED[w * 5 + 4];
            }
            float* gp = g_blk + ((size_t)blockIdx.x * NT + t) * 5;
            gp[0] = s0; gp[1] = s1; gp[2] = s2; gp[3] = s3; gp[4] = s4;
        }

        // ---- G: LSTM gates GEMM (conflict-free staged) + cell update ----
        {
            u64 acc[4][2];
            #pragma unroll
            for (int j = 0; j < 4; ++j) { acc[j][0] = 0ull; acc[j][1] = 0ull; }
            for (int ch = 0; ch < GCH; ++ch) {
                float* wb = sWB + (ch & 1) * GSTG;
                #pragma unroll
                for (int i = 0; i < 5; ++i)
                    *reinterpret_cast<float4*>(wb + gDst[i]) = gpre[i];
                if (ch + 1 < GCH) {
                    #pragma unroll
                    for (int i = 0; i < 5; ++i)
                        gpre[i] = gsrc4[(ch + 1) * (GRCH / 4) + tid + i * NTHR];
                }
                __syncthreads();
                const float* wrow = wb + uG * 84;
                int kbase = ch * GKC;
                #pragma unroll
                for (int kk0 = 0; kk0 < GKC; kk0 += 4) {
                    float4 w0 = *reinterpret_cast<const float4*>(wrow + 0 * 20 + kk0);
                    float4 w1 = *reinterpret_cast<const float4*>(wrow + 1 * 20 + kk0);
                    float4 w2 = *reinterpret_cast<const float4*>(wrow + 2 * 20 + kk0);
                    float4 w3 = *reinterpret_cast<const float4*>(wrow + 3 * 20 + kk0);
                    #pragma unroll
                    for (int kk = 0; kk < 4; ++kk) {
                        ulonglong2 a2 = *reinterpret_cast<const ulonglong2*>(
                            &sACT[(kbase + kk0 + kk) * 16 + r0g]);
                        u64 b0 = bcast2(getc4(w0, kk));
                        fma2(acc[0][0], a2.x, b0); fma2(acc[0][1], a2.y, b0);
                        u64 b1 = bcast2(getc4(w1, kk));
                        fma2(acc[1][0], a2.x, b1); fma2(acc[1][1], a2.y, b1);
                        u64 b2 = bcast2(getc4(w2, kk));
                        fma2(acc[2][0], a2.x, b2); fma2(acc[2][1], a2.y, b2);
                        u64 b3 = bcast2(getc4(w3, kk));
                        fma2(acc[3][0], a2.x, b3); fma2(acc[3][1], a2.y, b3);
                    }
                }
            }
            // epilogue: cell update -> registers (stored after barrier, next t)
            float bi = sBIA[B_PBG + uG * 4 + 0];
            float bf = sBIA[B_PBG + uG * 4 + 1];
            float bg = sBIA[B_PBG + uG * 4 + 2];
            float bo = sBIA[B_PBG + uG * 4 + 3];
            #pragma unroll
            for (int pp = 0; pp < 2; ++pp) {
                float2 gi2 = unpack2(acc[0][pp]);
                float2 gf2 = unpack2(acc[1][pp]);
                float2 gg2 = unpack2(acc[2][pp]);
                float2 go2 = unpack2(acc[3][pp]);
                #pragma unroll
                for (int rr = 0; rr < 2; ++rr) {
                    int r = r0g + pp * 2 + rr;
                    float gi_ = ((rr == 0) ? gi2.x : gi2.y) + bi;
                    float gf_ = ((rr == 0) ? gf2.x : gf2.y) + bf;
                    float gg_ = ((rr == 0) ? gg2.x : gg2.y) + bg;
                    float go_ = ((rr == 0) ? go2.x : go2.y) + bo;
                    float cn = sigmoidf_(gf_) * sCT[uG * 17 + r]
                             + sigmoidf_(gi_) * ftanh_(gg_);
                    sCT[uG * 17 + r] = cn;
                    hnew[pp * 2 + rr] = sigmoidf_(go_) * ftanh_(cn);
                }
            }
            have_h = true;
        }
        __syncthreads();
    }

    // ---- fused finalize: last block reduces g_blk -> out_loss ----
    __threadfence();
    __shared__ int sIsLast;
    if (tid == 0) {
        int ticket = atomicAdd(&g_done, 1);
        sIsLast = (ticket == NBLK - 1) ? 1 : 0;
    }
    __syncthreads();
    if (sIsLast) {
        __shared__ double terms[NT];
        for (int t = wrp; t < NT; t += 16) {
            double s0 = 0.0, s1 = 0.0, s2 = 0.0, s3 = 0.0, s4 = 0.0;
            for (int b = lane; b < NBLK; b += 32) {
                const float* gp = g_blk + ((size_t)b * NT + t) * 5;
                s0 += (double)gp[0]; s1 += (double)gp[1]; s2 += (double)gp[2];
                s3 += (double)gp[3]; s4 += (double)gp[4];
            }
            #pragma unroll
            for (int o = 16; o > 0; o >>= 1) {
                s0 += __shfl_down_sync(0xffffffffu, s0, o);
                s1 += __shfl_down_sync(0xffffffffu, s1, o);
                s2 += __shfl_down_sync(0xffffffffu, s2, o);
                s3 += __shfl_down_sync(0xffffffffu, s3, o);
                s4 += __shfl_down_sync(0xffffffffu, s4, o);
            }
            if (lane == 0) {
                double pm = s0 + 1e-5;
                terms[t] = (s1 + s2 + s4 + s3 / (double)NE) / pm;
            }
        }
        __syncthreads();
        if (tid == 0) {
            double s = 0.0;
            for (int i = 0; i < NT; ++i) s += terms[i];
            out_loss[0] = (float)(s / (double)NT);
        }
    }
}

extern "C" void kernel_launch(void* const* d_in, const int* in_sizes, int n_in,
                              void* d_out, int out_size)
{
    const float* x      = (const float*)d_in[0];
    const float* mask   = (const float*)d_in[1];
    const float* delta  = (const float*)d_in[2];
    const float* w_dh   = (const float*)d_in[3];
    const float* b_dh   = (const float*)d_in[4];
    const float* w_dx   = (const float*)d_in[5];
    const float* b_dx   = (const float*)d_in[6];
    const float* w_hr   = (const float*)d_in[7];
    const float* b_hr   = (const float*)d_in[8];
    const float* w_fr   = (const float*)d_in[9];
    const float* b_fr   = (const float*)d_in[10];
    const float* w_comb = (const float*)d_in[11];
    const float* b_comb = (const float*)d_in[12];
    const float* w_ih   = (const float*)d_in[13];
    const float* w_hh   = (const float*)d_in[14];
    const float* b_ih   = (const float*)d_in[15];
    const float* b_hh   = (const float*)d_in[16];

    float* out = (float*)d_out;
    float* out_imp = out + 1;
    float* out_ens = out_imp + (size_t)NBATCH * NT * NC;

    const int smem_bytes = SMEM_FLOATS * (int)sizeof(float);
    cudaFuncSetAttribute(brits_main, cudaFuncAttributeMaxDynamicSharedMemorySize,
                         smem_bytes);

    brits_prep<<<256, 256>>>(w_fr, w_comb, w_ih, w_hh, b_ih, b_hh, w_dx);
    brits_main<<<NBLK, NTHR, smem_bytes>>>(
        x, mask, delta, w_dh, b_dh, b_dx, w_hr, b_hr, b_fr, b_comb,
        out, out_imp, out_ens);
}

// round 16
// speedup vs baseline: 1.7635x; 1.7635x over previous
#include <cuda_runtime.h>

#define NBATCH 2048
#define NT     48
#define NC     35
#define NE     19
#define NH     128
#define RROWS  16
#define NTHR   512
#define NBLK   128
#define NPAIR  665
// G GEMM: 512 gate-rows x 200 k (70 cc2 + 2 pad + 128 h), chunks of 20 k
#define GKC    20
#define GCH    10
#define GRCH   (NH * 4 * GKC)     // 10240 raw floats per chunk
#define GSTG   (NH * 84)          // 10752 staged floats (row 80 -> 84, conflict-free)
// E GEMM: 672 pairs x 72 k, chunks of 12 k
#define EKC    12
#define ECH    6
#define ERCH   (672 * EKC)        // 8064 raw floats per chunk
#define ESTG   (112 * 76)         // 8512 staged floats (group 72 -> 76, conflict-free)

typedef unsigned long long u64;

// ---------------- prepared weights (device scratch) ----------------
__device__ float PW_G[GCH * GRCH];    // [ch][u(128)][gate(4)][kk(20)]
__device__ float PW_E[ECH * ERCH];    // [ch][pair(672)][kk(12)]
__device__ float PW_FRd[NC * NC];
__device__ float PB_Gd[NH * 4];
__device__ float PDXd[NC];
__device__ float g_blk[NBLK * NT * 5];
__device__ int   g_done;

// ---------------- smem layout (floats) ----------------
#define O_AA   0
#define O_AB   3200
#define O_CT   6400
#define O_DTP  8576
#define O_XM   9136
#define O_XZ   10328
#define O_XCP  11520
#define O_CAT  12080
#define O_TPT  13360
#define O_WDH  24784
#define O_WHR  29264
#define O_WFR  33744
#define O_BIA  34976
#define O_SRED 36448
#define O_WB   36528
#define SMEM_FLOATS (O_WB + 2 * GSTG)   // 58032 floats = 232128 B (no static smem!)

#define B_BDH 0
#define B_BHR 128
#define B_BFR 168
#define B_BDX 208
#define B_PDX 248
#define B_BCB 288
#define B_PBG 960

// ---------------- helpers ----------------
static __device__ __forceinline__ u64 bcast2(float w) {
    u64 r; asm("mov.b64 %0, {%1, %1};" : "=l"(r) : "f"(w)); return r;
}
static __device__ __forceinline__ void fma2(u64& acc, u64 a, u64 b) {
    asm("fma.rn.f32x2 %0, %1, %2, %0;" : "+l"(acc) : "l"(a), "l"(b));
}
static __device__ __forceinline__ float2 unpack2(u64 v) {
    float2 f; asm("mov.b64 {%0, %1}, %2;" : "=f"(f.x), "=f"(f.y) : "l"(v)); return f;
}
static __device__ __forceinline__ float sigmoidf_(float v) {
    return 1.0f / (1.0f + __expf(-v));
}
static __device__ __forceinline__ float ftanh_(float v) {
    return 1.0f - __fdividef(2.0f, __expf(2.0f * v) + 1.0f);
}
static __device__ __forceinline__ float getc4(float4 v, int kk) {
    return (kk == 0) ? v.x : (kk == 1) ? v.y : (kk == 2) ? v.z : v.w;
}

// ---------------- prep ----------------
__global__ void brits_prep(const float* __restrict__ w_fr,
                           const float* __restrict__ w_comb,
                           const float* __restrict__ w_ih,
                           const float* __restrict__ w_hh,
                           const float* __restrict__ b_ih,
                           const float* __restrict__ b_hh,
                           const float* __restrict__ w_dx)
{
    int i0 = blockIdx.x * blockDim.x + threadIdx.x;
    int n = gridDim.x * blockDim.x;
    if (i0 == 0) g_done = 0;
    for (int i = i0; i < GCH * GRCH; i += n) {
        int c = i / GRCH, rem = i - c * GRCH;
        int u = rem / 80, rem2 = rem - u * 80;
        int j = rem2 / GKC, kk = rem2 - j * GKC;
        int k = c * GKC + kk;
        float v = 0.0f;
        if (k < 70)       v = w_ih[(j * NH + u) * 70 + k];
        else if (k >= 72) v = w_hh[(j * NH + u) * NH + (k - 72)];
        PW_G[i] = v;
    }
    for (int i = i0; i < ECH * ERCH; i += n) {
        int c = i / ERCH, rem = i - c * ERCH;
        int p = rem / EKC, kk = rem - p * EKC;
        int k = c * EKC + kk;
        PW_E[i] = (p < NPAIR && k < 70) ? w_comb[p * 70 + k] : 0.0f;
    }
    for (int i = i0; i < NC * NC; i += n) {
        int r = i / NC, c = i - r * NC;
        PW_FRd[i] = (r == c) ? 0.0f : w_fr[i];
    }
    for (int i = i0; i < NH * 4; i += n) {
        int u = i >> 2, j = i & 3;
        PB_Gd[i] = b_ih[j * NH + u] + b_hh[j * NH + u];
    }
    for (int i = i0; i < NC; i += n) PDXd[i] = w_dx[i * NC + i];
}

// ---------------- main (+fused finalize, zero static smem) ----------------
__global__ __launch_bounds__(NTHR, 1)
void brits_main(const float* __restrict__ x, const float* __restrict__ mask,
                const float* __restrict__ delta,
                const float* __restrict__ w_dh, const float* __restrict__ b_dh,
                const float* __restrict__ b_dx,
                const float* __restrict__ w_hr, const float* __restrict__ b_hr,
                const float* __restrict__ b_fr,
                const float* __restrict__ b_comb,
                float* __restrict__ out_loss,
                float* __restrict__ out_imp, float* __restrict__ out_ens)
{
    extern __shared__ float sm[];
    float* sAA  = sm + O_AA;
    float* sAB  = sm + O_AB;
    float* sCT  = sm + O_CT;
    float* sDTP = sm + O_DTP;
    float* sXM  = sm + O_XM;
    float* sXZ  = sm + O_XZ;
    float* sXCP = sm + O_XCP;
    float* sCAT = sm + O_CAT;
    float* sTPT = sm + O_TPT;
    float* sWDH = sm + O_WDH;
    float* sWHR = sm + O_WHR;
    float* sWFR = sm + O_WFR;
    float* sBIA = sm + O_BIA;
    float* sRED = sm + O_SRED;
    float* sWB  = sm + O_WB;

    const int tid  = threadIdx.x;
    const int lane = tid & 31;
    const int wrp  = tid >> 5;
    const int rowBase = blockIdx.x * RROWS;

    // one-time resident weights/biases + state init
    for (int i = tid; i < NH * NC; i += NTHR) sWDH[i] = w_dh[i];
    for (int i = tid; i < NC * NH; i += NTHR) sWHR[i] = w_hr[i];
    for (int i = tid; i < NC * NC; i += NTHR) sWFR[i] = PW_FRd[i];
    for (int i = tid; i < NH; i += NTHR) sBIA[B_BDH + i] = b_dh[i];
    for (int i = tid; i < NC; i += NTHR) {
        sBIA[B_BHR + i] = b_hr[i];
        sBIA[B_BFR + i] = b_fr[i];
        sBIA[B_BDX + i] = b_dx[i];
        sBIA[B_PDX + i] = PDXd[i];
    }
    for (int i = tid; i < NPAIR; i += NTHR) sBIA[B_BCB + i] = b_comb[i];
    for (int i = tid; i < NH * 4; i += NTHR) sBIA[B_PBG + i] = PB_Gd[i];
    for (int i = tid; i < 3200; i += NTHR) { sAA[i] = 0.f; sAB[i] = 0.f; }
    for (int i = tid; i < NH * 17; i += NTHR) sCT[i] = 0.f;
    for (int i = tid; i < 160; i += NTHR) sCAT[70 * 16 + i] = 0.f;
    __syncthreads();

    float* aCur = sAA;
    float* aNxt = sAB;

    const int pgrp = tid >> 2;          // E: 6-pair group (valid < 112 -> tid < 448)
    const int r0e  = (tid & 3) * 4;
    const int uG   = tid >> 2;          // G: LSTM unit
    const int r0g  = (tid & 3) * 4;

    // staged-copy destinations (padded strides)
    int gDst[5], eDst[4];
    #pragma unroll
    for (int i = 0; i < 5; ++i) {
        int f = tid + i * NTHR;         // float4 index 0..2559
        int u = f / 20, rem = f - u * 20;
        gDst[i] = u * 84 + rem * 4;
    }
    #pragma unroll
    for (int i = 0; i < 4; ++i) {
        int f = tid + i * NTHR;         // float4 index, valid < 2016
        if (f < ERCH / 4) {
            int o = f * 4;
            int p = o / 12, kk = o - p * 12;
            int q = p / 6, jj = p - q * 6;
            eDst[i] = q * 76 + jj * 12 + kk;
        } else eDst[i] = -1;
    }
    const float4* gsrc4 = reinterpret_cast<const float4*>(PW_G);
    const float4* esrc4 = reinterpret_cast<const float4*>(PW_E);

    // hoisted ensemble-write indices (fixed per thread)
    const int pA = tid;                 // < 665 always
    const int nA = pA / NC;  const int cA = pA - nA * NC;
    const size_t offA = (size_t)nA * NT * NC + cA;
    const int pB = tid + NTHR;
    const bool hasB = (pB < NPAIR);
    const int nB = hasB ? (pB / NC) : 0;
    const int cB = hasB ? (pB - nB * NC) : 0;
    const size_t offB = (size_t)nB * NT * NC + cB;

    for (int t = 0; t < NT; ++t) {
        float lm = 0.f, l1 = 0.f, l2 = 0.f, lq = 0.f, l4 = 0.f;

        // ---- A: transposed loads ----
        for (int i = tid; i < RROWS * NC; i += NTHR) {
            int r = i / NC, c = i - r * NC;
            size_t gi = ((size_t)(rowBase + r) * NT + t) * NC + c;
            float xv = x[gi], mv = mask[gi], dv = delta[gi];
            sDTP[c * 16 + r] = dv;
            sXM[(c * 17 + r) * 2 + 0] = xv;
            sXM[(c * 17 + r) * 2 + 1] = mv;
            sCAT[(NC + c) * 16 + r] = mv;
            lm += mv;
        }
        __syncthreads();

        // ---- B1: gamma_x ----
        for (int i = tid; i < NC * 16; i += NTHR) {
            int c = i >> 4, r = i & 15;
            float gx = __expf(-fmaxf(sDTP[c * 16 + r] * sBIA[B_PDX + c]
                                     + sBIA[B_BDX + c], 0.f));
            sCAT[c * 16 + r] = gx;
        }
        // ---- B2: gamma_h decay ----
        for (int task = tid; task < NH * 8; task += NTHR) {
            int h = task >> 3, rg = task & 7, r0 = rg * 2;
            u64 a0 = 0ull, a1 = 0ull;
            const float* wr = sWDH + h * NC;
            #pragma unroll
            for (int k = 0; k < NC; ++k) {
                u64 d = *reinterpret_cast<const u64*>(&sDTP[k * 16 + r0]);
                if (k & 1) fma2(a1, d, bcast2(wr[k]));
                else       fma2(a0, d, bcast2(wr[k]));
            }
            float2 s0 = unpack2(a0), s1 = unpack2(a1);
            float bb = sBIA[B_BDH + h];
            aCur[(72 + h) * 16 + r0 + 0] *= __expf(-fmaxf(s0.x + s1.x + bb, 0.f));
            aCur[(72 + h) * 16 + r0 + 1] *= __expf(-fmaxf(s0.y + s1.y + bb, 0.f));
        }
        __syncthreads();

        // ---- C: x_h ----
        if (tid < NC * 8) {
            int c = tid >> 3, rg = tid & 7, r0 = rg * 2;
            u64 a0 = 0ull, a1 = 0ull;
            const float* wr = sWHR + c * NH;
            #pragma unroll 4
            for (int k0 = 0; k0 < NH; k0 += 4) {
                float4 w = *reinterpret_cast<const float4*>(wr + k0);
                u64 h0 = *reinterpret_cast<const u64*>(&aCur[(72 + k0 + 0) * 16 + r0]);
                u64 h1 = *reinterpret_cast<const u64*>(&aCur[(72 + k0 + 1) * 16 + r0]);
                u64 h2 = *reinterpret_cast<const u64*>(&aCur[(72 + k0 + 2) * 16 + r0]);
                u64 h3 = *reinterpret_cast<const u64*>(&aCur[(72 + k0 + 3) * 16 + r0]);
                fma2(a0, h0, bcast2(w.x)); fma2(a1, h1, bcast2(w.y));
                fma2(a0, h2, bcast2(w.z)); fma2(a1, h3, bcast2(w.w));
            }
            float2 s0 = unpack2(a0), s1 = unpack2(a1);
            float bb = sBIA[B_BHR + c];
            float xh[2] = {s0.x + s1.x + bb, s0.y + s1.y + bb};
            #pragma unroll
            for (int rr = 0; rr < 2; ++rr) {
                int r = r0 + rr;
                sXZ[(c * 17 + r) * 2 + 0] = xh[rr];
                float xt = sXM[(c * 17 + r) * 2 + 0];
                float mt = sXM[(c * 17 + r) * 2 + 1];
                l1 += fabsf(xt - xh[rr]) * mt;
                sXCP[c * 16 + r] = mt * xt + (1.f - mt) * xh[rr];
            }
        }
        __syncthreads();

        // ---- E chunk-0 prefetch (hidden under D) ----
        float4 epre[4];
        #pragma unroll
        for (int i = 0; i < 4; ++i)
            if (tid + i * NTHR < ERCH / 4) epre[i] = esrc4[tid + i * NTHR];

        // ---- D: z_h ----
        if (tid < NC * 8) {
            int c = tid >> 3, rg = tid & 7, r0 = rg * 2;
            u64 a0 = 0ull, a1 = 0ull;
            const float* wr = sWFR + c * NC;
            #pragma unroll
            for (int k = 0; k < NC; ++k) {
                u64 xp = *reinterpret_cast<const u64*>(&sXCP[k * 16 + r0]);
                if (k & 1) fma2(a1, xp, bcast2(wr[k]));
                else       fma2(a0, xp, bcast2(wr[k]));
            }
            float2 s0 = unpack2(a0), s1 = unpack2(a1);
            float bb = sBIA[B_BFR + c];
            #pragma unroll
            for (int rr = 0; rr < 2; ++rr) {
                int r = r0 + rr;
                float z = ((rr == 0) ? (s0.x + s1.x) : (s0.y + s1.y)) + bb;
                float xh = sXZ[(c * 17 + r) * 2 + 0];
                sXZ[(c * 17 + r) * 2 + 1] = z - xh;
                float xt = sXM[(c * 17 + r) * 2 + 0];
                float mt = sXM[(c * 17 + r) * 2 + 1];
                l2 += fabsf(xt - z) * mt;
            }
        }
        __syncthreads();

        // ---- E: alpha GEMM (padded staging, conflict-free weight LDS) ----
        {
            u64 acc[6][2];
            #pragma unroll
            for (int j = 0; j < 6; ++j) { acc[j][0] = 0ull; acc[j][1] = 0ull; }
            for (int ch = 0; ch < ECH; ++ch) {
                float* wb = sWB + (ch & 1) * GSTG;
                #pragma unroll
                for (int i = 0; i < 4; ++i)
                    if (eDst[i] >= 0)
                        *reinterpret_cast<float4*>(wb + eDst[i]) = epre[i];
                if (ch + 1 < ECH) {
                    #pragma unroll
                    for (int i = 0; i < 4; ++i)
                        if (tid + i * NTHR < ERCH / 4)
                            epre[i] = esrc4[(ch + 1) * (ERCH / 4) + tid + i * NTHR];
                }
                __syncthreads();
                if (tid < 448) {
                    const float* wrow = wb + pgrp * 76;
                    int kbase = ch * EKC;
                    #pragma unroll
                    for (int kk0 = 0; kk0 < EKC; kk0 += 4) {
                        float4 w[6];
                        #pragma unroll
                        for (int j = 0; j < 6; ++j)
                            w[j] = *reinterpret_cast<const float4*>(wrow + j * 12 + kk0);
                        #pragma unroll
                        for (int kk = 0; kk < 4; ++kk) {
                            ulonglong2 a2 = *reinterpret_cast<const ulonglong2*>(
                                &sCAT[(kbase + kk0 + kk) * 16 + r0e]);
                            #pragma unroll
                            for (int j = 0; j < 6; ++j) {
                                u64 b = bcast2(getc4(w[j], kk));
                                fma2(acc[j][0], a2.x, b);
                                fma2(acc[j][1], a2.y, b);
                            }
                        }
                    }
                }
            }
            // epilogue
            if (tid < 448) {
                #pragma unroll
                for (int j = 0; j < 6; ++j) {
                    int p = pgrp * 6 + j;
                    if (p < NPAIR) {
                        int n = p / NC, c = p - n * NC;
                        float bc = sBIA[B_BCB + p];
                        float qn = (float)(n + 1) * 0.05f;
                        #pragma unroll
                        for (int pp = 0; pp < 2; ++pp) {
                            float2 av = unpack2(acc[j][pp]);
                            #pragma unroll
                            for (int rr = 0; rr < 2; ++rr) {
                                int r = r0e + pp * 2 + rr;
                                float alpha = ((rr == 0) ? av.x : av.y) + bc;
                                float xh  = sXZ[(c * 17 + r) * 2 + 0];
                                float dzh = sXZ[(c * 17 + r) * 2 + 1];
                                float tp = xh + alpha * dzh;
                                float xt = sXM[(c * 17 + r) * 2 + 0];
                                float mt = sXM[(c * 17 + r) * 2 + 1];
                                float wq = (xt <= tp) ? (1.f - qn) : qn;
                                lq += fabsf(tp - xt) * mt * wq;
                                sTPT[p * 17 + r] = tp;
                            }
                        }
                    }
                }
            }
        }
        __syncthreads();

        // ---- G chunk-0 prefetch (hidden under F) ----
        float4 gpre[5];
        #pragma unroll
        for (int i = 0; i < 5; ++i)
            gpre[i] = gsrc4[tid + i * NTHR];

        // ---- F: ensemble mean, imp out, cc2 ----
        for (int i = tid; i < NC * 16; i += NTHR) {
            int c = i >> 4, r = i & 15;
            float s = 0.f;
            #pragma unroll
            for (int n = 0; n < NE; ++n) s += sTPT[(n * NC + c) * 17 + r];
            float mean = s * (1.0f / (float)NE);
            float xt = sXM[(c * 17 + r) * 2 + 0];
            float mt = sXM[(c * 17 + r) * 2 + 1];
            l4 += fabsf(xt - mean) * mt;
            float cc = mt * xt + (1.f - mt) * mean;
            out_imp[((size_t)(rowBase + r) * NT + t) * NC + c] = cc;
            aCur[c * 16 + r] = cc;
            aCur[(NC + c) * 16 + r] = mt;
        }
        // ---- ens writes (hoisted indices, no divides) ----
        {
            size_t gb = (size_t)rowBase * NE * NT * NC + (size_t)t * NC;
            for (int r = 0; r < RROWS; ++r, gb += (size_t)NE * NT * NC) {
                float2 xm = *reinterpret_cast<const float2*>(&sXM[(cA * 17 + r) * 2]);
                out_ens[gb + offA] = xm.y * xm.x + (1.f - xm.y) * sTPT[pA * 17 + r];
                if (hasB) {
                    float2 xb = *reinterpret_cast<const float2*>(&sXM[(cB * 17 + r) * 2]);
                    out_ens[gb + offB] = xb.y * xb.x + (1.f - xb.y) * sTPT[pB * 17 + r];
                }
            }
        }
        // ---- loss reduce ----
        {
            float v0 = lm, v1 = l1, v2 = l2, v3 = lq, v4 = l4;
            #pragma unroll
            for (int o = 16; o > 0; o >>= 1) {
                v0 += __shfl_down_sync(0xffffffffu, v0, o);
                v1 += __shfl_down_sync(0xffffffffu, v1, o);
                v2 += __shfl_down_sync(0xffffffffu, v2, o);
                v3 += __shfl_down_sync(0xffffffffu, v3, o);
                v4 += __shfl_down_sync(0xffffffffu, v4, o);
            }
            if (lane == 0) {
                sRED[wrp * 5 + 0] = v0; sRED[wrp * 5 + 1] = v1;
                sRED[wrp * 5 + 2] = v2; sRED[wrp * 5 + 3] = v3;
                sRED[wrp * 5 + 4] = v4;
            }
        }
        __syncthreads();
        if (tid == 0) {
            float s0 = 0.f, s1 = 0.f, s2 = 0.f, s3 = 0.f, s4 = 0.f;
            for (int w = 0; w < NTHR / 32; ++w) {
                s0 += sRED[w * 5 + 0]; s1 += sRED[w * 5 + 1];
                s2 += sRED[w * 5 + 2]; s3 += sRED[w * 5 + 3];
                s4 += sRED[w * 5 + 4];
            }
            float* gp = g_blk + ((size_t)blockIdx.x * NT + t) * 5;
            gp[0] = s0; gp[1] = s1; gp[2] = s2; gp[3] = s3; gp[4] = s4;
        }

        // ---- G: LSTM gates GEMM (padded staging, conflict-free) + cell update ----
        {
            u64 acc[4][2];
            #pragma unroll
            for (int j = 0; j < 4; ++j) { acc[j][0] = 0ull; acc[j][1] = 0ull; }
            for (int ch = 0; ch < GCH; ++ch) {
                float* wb = sWB + (ch & 1) * GSTG;
                #pragma unroll
                for (int i = 0; i < 5; ++i)
                    *reinterpret_cast<float4*>(wb + gDst[i]) = gpre[i];
                if (ch + 1 < GCH) {
                    #pragma unroll
                    for (int i = 0; i < 5; ++i)
                        gpre[i] = gsrc4[(ch + 1) * (GRCH / 4) + tid + i * NTHR];
                }
                __syncthreads();
                const float* wrow = wb + uG * 84;
                int kbase = ch * GKC;
                #pragma unroll
                for (int kk0 = 0; kk0 < GKC; kk0 += 4) {
                    float4 w0 = *reinterpret_cast<const float4*>(wrow + 0 * 20 + kk0);
                    float4 w1 = *reinterpret_cast<const float4*>(wrow + 1 * 20 + kk0);
                    float4 w2 = *reinterpret_cast<const float4*>(wrow + 2 * 20 + kk0);
                    float4 w3 = *reinterpret_cast<const float4*>(wrow + 3 * 20 + kk0);
                    #pragma unroll
                    for (int kk = 0; kk < 4; ++kk) {
                        ulonglong2 a2 = *reinterpret_cast<const ulonglong2*>(
                            &aCur[(kbase + kk0 + kk) * 16 + r0g]);
                        u64 b0 = bcast2(getc4(w0, kk));
                        fma2(acc[0][0], a2.x, b0); fma2(acc[0][1], a2.y, b0);
                        u64 b1 = bcast2(getc4(w1, kk));
                        fma2(acc[1][0], a2.x, b1); fma2(acc[1][1], a2.y, b1);
                        u64 b2 = bcast2(getc4(w2, kk));
                        fma2(acc[2][0], a2.x, b2); fma2(acc[2][1], a2.y, b2);
                        u64 b3 = bcast2(getc4(w3, kk));
                        fma2(acc[3][0], a2.x, b3); fma2(acc[3][1], a2.y, b3);
                    }
                }
            }
            // epilogue: cell update
            float bi = sBIA[B_PBG + uG * 4 + 0];
            float bf = sBIA[B_PBG + uG * 4 + 1];
            float bg = sBIA[B_PBG + uG * 4 + 2];
            float bo = sBIA[B_PBG + uG * 4 + 3];
            #pragma unroll
            for (int pp = 0; pp < 2; ++pp) {
                float2 gi2 = unpack2(acc[0][pp]);
                float2 gf2 = unpack2(acc[1][pp]);
                float2 gg2 = unpack2(acc[2][pp]);
                float2 go2 = unpack2(acc[3][pp]);
                #pragma unroll
                for (int rr = 0; rr < 2; ++rr) {
                    int r = r0g + pp * 2 + rr;
                    float gi_ = ((rr == 0) ? gi2.x : gi2.y) + bi;
                    float gf_ = ((rr == 0) ? gf2.x : gf2.y) + bf;
                    float gg_ = ((rr == 0) ? gg2.x : gg2.y) + bg;
                    float go_ = ((rr == 0) ? go2.x : go2.y) + bo;
                    float cn = sigmoidf_(gf_) * sCT[uG * 17 + r]
                             + sigmoidf_(gi_) * ftanh_(gg_);
                    sCT[uG * 17 + r] = cn;
                    aNxt[(72 + uG) * 16 + r] = sigmoidf_(go_) * ftanh_(cn);
                }
            }
        }
        __syncthreads();
        float* tmp = aCur; aCur = aNxt; aNxt = tmp;
    }

    // ---- fused finalize: last block reduces g_blk -> out_loss ----
    // scratch aliases dynamic smem (sTPT region is dead; 8-byte aligned offset)
    __threadfence();
    int* sIsLast = reinterpret_cast<int*>(sRED + 79);
    double* terms = reinterpret_cast<double*>(sm + O_TPT);
    if (tid == 0) {
        int ticket = atomicAdd(&g_done, 1);
        *sIsLast = (ticket == NBLK - 1) ? 1 : 0;
    }
    __syncthreads();
    if (*sIsLast) {
        for (int t = wrp; t < NT; t += 16) {
            double s0 = 0.0, s1 = 0.0, s2 = 0.0, s3 = 0.0, s4 = 0.0;
            for (int b = lane; b < NBLK; b += 32) {
                const float* gp = g_blk + ((size_t)b * NT + t) * 5;
                s0 += (double)gp[0]; s1 += (double)gp[1]; s2 += (double)gp[2];
                s3 += (double)gp[3]; s4 += (double)gp[4];
            }
            #pragma unroll
            for (int o = 16; o > 0; o >>= 1) {
                s0 += __shfl_down_sync(0xffffffffu, s0, o);
                s1 += __shfl_down_sync(0xffffffffu, s1, o);
                s2 += __shfl_down_sync(0xffffffffu, s2, o);
                s3 += __shfl_down_sync(0xffffffffu, s3, o);
                s4 += __shfl_down_sync(0xffffffffu, s4, o);
            }
            if (lane == 0) {
                double pm = s0 + 1e-5;
                terms[t] = (s1 + s2 + s4 + s3 / (double)NE) / pm;
            }
        }
        __syncthreads();
        if (tid == 0) {
            double s = 0.0;
            for (int i = 0; i < NT; ++i) s += terms[i];
            out_loss[0] = (float)(s / (double)NT);
        }
    }
}

extern "C" void kernel_launch(void* const* d_in, const int* in_sizes, int n_in,
                              void* d_out, int out_size)
{
    const float* x      = (const float*)d_in[0];
    const float* mask   = (const float*)d_in[1];
    const float* delta  = (const float*)d_in[2];
    const float* w_dh   = (const float*)d_in[3];
    const float* b_dh   = (const float*)d_in[4];
    const float* w_dx   = (const float*)d_in[5];
    const float* b_dx   = (const float*)d_in[6];
    const float* w_hr   = (const float*)d_in[7];
    const float* b_hr   = (const float*)d_in[8];
    const float* w_fr   = (const float*)d_in[9];
    const float* b_fr   = (const float*)d_in[10];
    const float* w_comb = (const float*)d_in[11];
    const float* b_comb = (const float*)d_in[12];
    const float* w_ih   = (const float*)d_in[13];
    const float* w_hh   = (const float*)d_in[14];
    const float* b_ih   = (const float*)d_in[15];
    const float* b_hh   = (const float*)d_in[16];

    float* out = (float*)d_out;
    float* out_imp = out + 1;
    float* out_ens = out_imp + (size_t)NBATCH * NT * NC;

    const int smem_bytes = SMEM_FLOATS * (int)sizeof(float);
    cudaFuncSetAttribute(brits_main, cudaFuncAttributeMaxDynamicSharedMemorySize,
                         smem_bytes);

    brits_prep<<<256, 256>>>(w_fr, w_comb, w_ih, w_hh, b_ih, b_hh, w_dx);
    brits_main<<<NBLK, NTHR, smem_bytes>>>(
        x, mask, delta, w_dh, b_dh, b_dx, w_hr, b_hr, b_fr, b_comb,
        out, out_imp, out_ens);
}

// round 17
// speedup vs baseline: 1.7750x; 1.0065x over previous
#include <cuda_runtime.h>

#define NBATCH 2048
#define NT     48
#define NC     35
#define NE     19
#define NH     128
#define RROWS  16
#define NTHR   512
#define NBLK   128
#define NPAIR  665
// G GEMM: 512 gate-rows x 200 k (70 cc2 + 2 pad + 128 h), chunks of 20 k
#define GKC    20
#define GCH    10
#define GRCH   (NH * 4 * GKC)     // 10240 raw floats per chunk (shuffled order in gmem)
#define GSTG   (NH * 84)          // 10752 staged floats (row 80 -> 84, conflict-free)
// E GEMM: 672 pairs x 72 k, chunks of 12 k
#define EKC    12
#define ECH    6
#define ERCH   (672 * EKC)        // 8064 raw floats per chunk (shuffled order in gmem)
#define ESTG   (112 * 76)         // 8512 staged floats (group 72 -> 76, conflict-free)

typedef unsigned long long u64;

// ---------------- prepared weights (device scratch) ----------------
__device__ float PW_G[GCH * GRCH];    // shuffled: see prep
__device__ float PW_E[ECH * ERCH];    // shuffled: see prep
__device__ float PW_FRd[NC * NC];
__device__ float PB_Gd[NH * 4];
__device__ float PDXd[NC];
__device__ float g_blk[NBLK * NT * 5];
__device__ int   g_done;

// ---------------- smem layout (floats) ----------------
#define O_AA   0
#define O_AB   3200
#define O_CT   6400
#define O_DTP  8576
#define O_XM   9136
#define O_XZ   10328
#define O_XCP  11520
#define O_CAT  12080
#define O_TPT  13360
#define O_WDH  24784
#define O_WHR  29264
#define O_WFR  33744
#define O_BIA  34976
#define O_SRED 36448
#define O_WB   36528
#define SMEM_FLOATS (O_WB + 2 * GSTG)   // 58032 floats = 232128 B (no static smem)

#define B_BDH 0
#define B_BHR 128
#define B_BFR 168
#define B_BDX 208
#define B_PDX 248
#define B_BCB 288
#define B_PBG 960

// ---------------- helpers ----------------
static __device__ __forceinline__ u64 bcast2(float w) {
    u64 r; asm("mov.b64 %0, {%1, %1};" : "=l"(r) : "f"(w)); return r;
}
static __device__ __forceinline__ void fma2(u64& acc, u64 a, u64 b) {
    asm("fma.rn.f32x2 %0, %1, %2, %0;" : "+l"(acc) : "l"(a), "l"(b));
}
static __device__ __forceinline__ float2 unpack2(u64 v) {
    float2 f; asm("mov.b64 {%0, %1}, %2;" : "=f"(f.x), "=f"(f.y) : "l"(v)); return f;
}
static __device__ __forceinline__ float sigmoidf_(float v) {
    return 1.0f / (1.0f + __expf(-v));
}
static __device__ __forceinline__ float ftanh_(float v) {
    return 1.0f - __fdividef(2.0f, __expf(2.0f * v) + 1.0f);
}
static __device__ __forceinline__ float getc4(float4 v, int kk) {
    return (kk == 0) ? v.x : (kk == 1) ? v.y : (kk == 2) ? v.z : v.w;
}

// ---------------- prep (weights written in staging-shuffled order) ----------------
// G: staged float4 s (0..2559) per chunk maps to dst u*21+rem (u=unit, rem=f4-in-row):
//    lane3 = s&7, oct = s>>3, uh = oct&15, rem = oct>>4, u = lane3 + 8*uh.
//    Within a warp-octet the STS bank-groups (21u+rem) mod 8 = (5*lane3+rem) mod 8
//    are all distinct -> conflict-free STS.128. LDG stays identity-coalesced.
// E: staged float4 s (0..2015): lane3 = s&7, oct = s>>3, qh = oct%14, j3 = oct/14,
//    q = lane3 + 8*qh; groups (19q+j3) mod 8 = (3*lane3+j3) mod 8 distinct.
__global__ void brits_prep(const float* __restrict__ w_fr,
                           const float* __restrict__ w_comb,
                           const float* __restrict__ w_ih,
                           const float* __restrict__ w_hh,
                           const float* __restrict__ b_ih,
                           const float* __restrict__ b_hh,
                           const float* __restrict__ w_dx)
{
    int i0 = blockIdx.x * blockDim.x + threadIdx.x;
    int n = gridDim.x * blockDim.x;
    if (i0 == 0) g_done = 0;
    for (int i = i0; i < GCH * GRCH; i += n) {
        int ch = i / GRCH, rem0 = i - ch * GRCH;
        int s = rem0 >> 2, ff = rem0 & 3;
        int lane3 = s & 7, oct = s >> 3;
        int uh = oct & 15, rem = oct >> 4;
        int u = lane3 + 8 * uh;
        int fpos = rem * 4 + ff;          // 0..79 within the unit row
        int j = fpos / GKC, kk = fpos - j * GKC;
        int k = ch * GKC + kk;
        float v = 0.0f;
        if (k < 70)       v = w_ih[(j * NH + u) * 70 + k];
        else if (k >= 72) v = w_hh[(j * NH + u) * NH + (k - 72)];
        PW_G[i] = v;
    }
    for (int i = i0; i < ECH * ERCH; i += n) {
        int ch = i / ERCH, rem0 = i - ch * ERCH;
        int s = rem0 >> 2, ff = rem0 & 3;
        int lane3 = s & 7, oct = s >> 3;
        int qh = oct % 14, j3 = oct / 14;
        int q = lane3 + 8 * qh;
        int fpos = j3 * 4 + ff;           // 0..71 within the 6-pair group
        int jj = fpos / EKC, kk = fpos - jj * EKC;
        int p = q * 6 + jj;
        int k = ch * EKC + kk;
        PW_E[i] = (p < NPAIR && k < 70) ? w_comb[p * 70 + k] : 0.0f;
    }
    for (int i = i0; i < NC * NC; i += n) {
        int r = i / NC, c = i - r * NC;
        PW_FRd[i] = (r == c) ? 0.0f : w_fr[i];
    }
    for (int i = i0; i < NH * 4; i += n) {
        int u = i >> 2, j = i & 3;
        PB_Gd[i] = b_ih[j * NH + u] + b_hh[j * NH + u];
    }
    for (int i = i0; i < NC; i += n) PDXd[i] = w_dx[i * NC + i];
}

// ---------------- main (+fused finalize, zero static smem) ----------------
__global__ __launch_bounds__(NTHR, 1)
void brits_main(const float* __restrict__ x, const float* __restrict__ mask,
                const float* __restrict__ delta,
                const float* __restrict__ w_dh, const float* __restrict__ b_dh,
                const float* __restrict__ b_dx,
                const float* __restrict__ w_hr, const float* __restrict__ b_hr,
                const float* __restrict__ b_fr,
                const float* __restrict__ b_comb,
                float* __restrict__ out_loss,
                float* __restrict__ out_imp, float* __restrict__ out_ens)
{
    extern __shared__ float sm[];
    float* sAA  = sm + O_AA;
    float* sAB  = sm + O_AB;
    float* sCT  = sm + O_CT;
    float* sDTP = sm + O_DTP;
    float* sXM  = sm + O_XM;
    float* sXZ  = sm + O_XZ;
    float* sXCP = sm + O_XCP;
    float* sCAT = sm + O_CAT;
    float* sTPT = sm + O_TPT;
    float* sWDH = sm + O_WDH;
    float* sWHR = sm + O_WHR;
    float* sWFR = sm + O_WFR;
    float* sBIA = sm + O_BIA;
    float* sRED = sm + O_SRED;
    float* sWB  = sm + O_WB;

    const int tid  = threadIdx.x;
    const int lane = tid & 31;
    const int wrp  = tid >> 5;
    const int rowBase = blockIdx.x * RROWS;

    // one-time resident weights/biases + state init
    for (int i = tid; i < NH * NC; i += NTHR) sWDH[i] = w_dh[i];
    for (int i = tid; i < NC * NH; i += NTHR) sWHR[i] = w_hr[i];
    for (int i = tid; i < NC * NC; i += NTHR) sWFR[i] = PW_FRd[i];
    for (int i = tid; i < NH; i += NTHR) sBIA[B_BDH + i] = b_dh[i];
    for (int i = tid; i < NC; i += NTHR) {
        sBIA[B_BHR + i] = b_hr[i];
        sBIA[B_BFR + i] = b_fr[i];
        sBIA[B_BDX + i] = b_dx[i];
        sBIA[B_PDX + i] = PDXd[i];
    }
    for (int i = tid; i < NPAIR; i += NTHR) sBIA[B_BCB + i] = b_comb[i];
    for (int i = tid; i < NH * 4; i += NTHR) sBIA[B_PBG + i] = PB_Gd[i];
    for (int i = tid; i < 3200; i += NTHR) { sAA[i] = 0.f; sAB[i] = 0.f; }
    for (int i = tid; i < NH * 17; i += NTHR) sCT[i] = 0.f;
    for (int i = tid; i < 160; i += NTHR) sCAT[70 * 16 + i] = 0.f;
    __syncthreads();

    float* aCur = sAA;
    float* aNxt = sAB;

    const int pgrp = tid >> 2;          // E: 6-pair group (valid < 112 -> tid < 448)
    const int r0e  = (tid & 3) * 4;
    const int uG   = tid >> 2;          // G: LSTM unit
    const int r0g  = (tid & 3) * 4;

    // staging destinations for shuffled source order (conflict-free STS octets)
    int gDst[5], eDst[4];
    #pragma unroll
    for (int i = 0; i < 5; ++i) {
        int f = tid + i * NTHR;         // float4 index 0..2559
        int lane3 = f & 7, oct = f >> 3;
        int u = lane3 + 8 * (oct & 15);
        int rem = oct >> 4;
        gDst[i] = u * 84 + rem * 4;
    }
    #pragma unroll
    for (int i = 0; i < 4; ++i) {
        int f = tid + i * NTHR;         // float4 index, valid < 2016
        if (f < ERCH / 4) {
            int lane3 = f & 7, oct = f >> 3;
            int q = lane3 + 8 * (oct % 14);
            int j3 = oct / 14;
            eDst[i] = q * 76 + j3 * 4;
        } else eDst[i] = -1;
    }
    const float4* gsrc4 = reinterpret_cast<const float4*>(PW_G);
    const float4* esrc4 = reinterpret_cast<const float4*>(PW_E);

    // hoisted ensemble-write indices (fixed per thread)
    const int pA = tid;                 // < 665 always
    const int nA = pA / NC;  const int cA = pA - nA * NC;
    const size_t offA = (size_t)nA * NT * NC + cA;
    const int pB = tid + NTHR;
    const bool hasB = (pB < NPAIR);
    const int nB = hasB ? (pB / NC) : 0;
    const int cB = hasB ? (pB - nB * NC) : 0;
    const size_t offB = (size_t)nB * NT * NC + cB;

    for (int t = 0; t < NT; ++t) {
        float lm = 0.f, l1 = 0.f, l2 = 0.f, lq = 0.f, l4 = 0.f;

        // ---- A: transposed loads ----
        for (int i = tid; i < RROWS * NC; i += NTHR) {
            int r = i / NC, c = i - r * NC;
            size_t gi = ((size_t)(rowBase + r) * NT + t) * NC + c;
            float xv = x[gi], mv = mask[gi], dv = delta[gi];
            sDTP[c * 16 + r] = dv;
            sXM[(c * 17 + r) * 2 + 0] = xv;
            sXM[(c * 17 + r) * 2 + 1] = mv;
            sCAT[(NC + c) * 16 + r] = mv;
            lm += mv;
        }
        __syncthreads();

        // ---- B1: gamma_x ----
        for (int i = tid; i < NC * 16; i += NTHR) {
            int c = i >> 4, r = i & 15;
            float gx = __expf(-fmaxf(sDTP[c * 16 + r] * sBIA[B_PDX + c]
                                     + sBIA[B_BDX + c], 0.f));
            sCAT[c * 16 + r] = gx;
        }
        // ---- B2: gamma_h decay ----
        for (int task = tid; task < NH * 8; task += NTHR) {
            int h = task >> 3, rg = task & 7, r0 = rg * 2;
            u64 a0 = 0ull, a1 = 0ull;
            const float* wr = sWDH + h * NC;
            #pragma unroll
            for (int k = 0; k < NC; ++k) {
                u64 d = *reinterpret_cast<const u64*>(&sDTP[k * 16 + r0]);
                if (k & 1) fma2(a1, d, bcast2(wr[k]));
                else       fma2(a0, d, bcast2(wr[k]));
            }
            float2 s0 = unpack2(a0), s1 = unpack2(a1);
            float bb = sBIA[B_BDH + h];
            aCur[(72 + h) * 16 + r0 + 0] *= __expf(-fmaxf(s0.x + s1.x + bb, 0.f));
            aCur[(72 + h) * 16 + r0 + 1] *= __expf(-fmaxf(s0.y + s1.y + bb, 0.f));
        }
        __syncthreads();

        // ---- C: x_h ----
        if (tid < NC * 8) {
            int c = tid >> 3, rg = tid & 7, r0 = rg * 2;
            u64 a0 = 0ull, a1 = 0ull;
            const float* wr = sWHR + c * NH;
            #pragma unroll 4
            for (int k0 = 0; k0 < NH; k0 += 4) {
                float4 w = *reinterpret_cast<const float4*>(wr + k0);
                u64 h0 = *reinterpret_cast<const u64*>(&aCur[(72 + k0 + 0) * 16 + r0]);
                u64 h1 = *reinterpret_cast<const u64*>(&aCur[(72 + k0 + 1) * 16 + r0]);
                u64 h2 = *reinterpret_cast<const u64*>(&aCur[(72 + k0 + 2) * 16 + r0]);
                u64 h3 = *reinterpret_cast<const u64*>(&aCur[(72 + k0 + 3) * 16 + r0]);
                fma2(a0, h0, bcast2(w.x)); fma2(a1, h1, bcast2(w.y));
                fma2(a0, h2, bcast2(w.z)); fma2(a1, h3, bcast2(w.w));
            }
            float2 s0 = unpack2(a0), s1 = unpack2(a1);
            float bb = sBIA[B_BHR + c];
            float xh[2] = {s0.x + s1.x + bb, s0.y + s1.y + bb};
            #pragma unroll
            for (int rr = 0; rr < 2; ++rr) {
                int r = r0 + rr;
                sXZ[(c * 17 + r) * 2 + 0] = xh[rr];
                float xt = sXM[(c * 17 + r) * 2 + 0];
                float mt = sXM[(c * 17 + r) * 2 + 1];
                l1 += fabsf(xt - xh[rr]) * mt;
                sXCP[c * 16 + r] = mt * xt + (1.f - mt) * xh[rr];
            }
        }
        __syncthreads();

        // ---- E chunk-0 prefetch (hidden under D) ----
        float4 epre[4];
        #pragma unroll
        for (int i = 0; i < 4; ++i)
            if (tid + i * NTHR < ERCH / 4) epre[i] = esrc4[tid + i * NTHR];

        // ---- D: z_h ----
        if (tid < NC * 8) {
            int c = tid >> 3, rg = tid & 7, r0 = rg * 2;
            u64 a0 = 0ull, a1 = 0ull;
            const float* wr = sWFR + c * NC;
            #pragma unroll
            for (int k = 0; k < NC; ++k) {
                u64 xp = *reinterpret_cast<const u64*>(&sXCP[k * 16 + r0]);
                if (k & 1) fma2(a1, xp, bcast2(wr[k]));
                else       fma2(a0, xp, bcast2(wr[k]));
            }
            float2 s0 = unpack2(a0), s1 = unpack2(a1);
            float bb = sBIA[B_BFR + c];
            #pragma unroll
            for (int rr = 0; rr < 2; ++rr) {
                int r = r0 + rr;
                float z = ((rr == 0) ? (s0.x + s1.x) : (s0.y + s1.y)) + bb;
                float xh = sXZ[(c * 17 + r) * 2 + 0];
                sXZ[(c * 17 + r) * 2 + 1] = z - xh;
                float xt = sXM[(c * 17 + r) * 2 + 0];
                float mt = sXM[(c * 17 + r) * 2 + 1];
                l2 += fabsf(xt - z) * mt;
            }
        }
        __syncthreads();

        // ---- E: alpha GEMM (conflict-free staging both ends) ----
        {
            u64 acc[6][2];
            #pragma unroll
            for (int j = 0; j < 6; ++j) { acc[j][0] = 0ull; acc[j][1] = 0ull; }
            for (int ch = 0; ch < ECH; ++ch) {
                float* wb = sWB + (ch & 1) * GSTG;
                #pragma unroll
                for (int i = 0; i < 4; ++i)
                    if (eDst[i] >= 0)
                        *reinterpret_cast<float4*>(wb + eDst[i]) = epre[i];
                if (ch + 1 < ECH) {
                    #pragma unroll
                    for (int i = 0; i < 4; ++i)
                        if (tid + i * NTHR < ERCH / 4)
                            epre[i] = esrc4[(ch + 1) * (ERCH / 4) + tid + i * NTHR];
                }
                __syncthreads();
                if (tid < 448) {
                    const float* wrow = wb + pgrp * 76;
                    int kbase = ch * EKC;
                    #pragma unroll
                    for (int kk0 = 0; kk0 < EKC; kk0 += 4) {
                        float4 w[6];
                        #pragma unroll
                        for (int j = 0; j < 6; ++j)
                            w[j] = *reinterpret_cast<const float4*>(wrow + j * 12 + kk0);
                        #pragma unroll
                        for (int kk = 0; kk < 4; ++kk) {
                            ulonglong2 a2 = *reinterpret_cast<const ulonglong2*>(
                                &sCAT[(kbase + kk0 + kk) * 16 + r0e]);
                            #pragma unroll
                            for (int j = 0; j < 6; ++j) {
                                u64 b = bcast2(getc4(w[j], kk));
                                fma2(acc[j][0], a2.x, b);
                                fma2(acc[j][1], a2.y, b);
                            }
                        }
                    }
                }
            }
            // epilogue
            if (tid < 448) {
                #pragma unroll
                for (int j = 0; j < 6; ++j) {
                    int p = pgrp * 6 + j;
                    if (p < NPAIR) {
                        int n = p / NC, c = p - n * NC;
                        float bc = sBIA[B_BCB + p];
                        float qn = (float)(n + 1) * 0.05f;
                        #pragma unroll
                        for (int pp = 0; pp < 2; ++pp) {
                            float2 av = unpack2(acc[j][pp]);
                            #pragma unroll
                            for (int rr = 0; rr < 2; ++rr) {
                                int r = r0e + pp * 2 + rr;
                                float alpha = ((rr == 0) ? av.x : av.y) + bc;
                                float xh  = sXZ[(c * 17 + r) * 2 + 0];
                                float dzh = sXZ[(c * 17 + r) * 2 + 1];
                                float tp = xh + alpha * dzh;
                                float xt = sXM[(c * 17 + r) * 2 + 0];
                                float mt = sXM[(c * 17 + r) * 2 + 1];
                                float wq = (xt <= tp) ? (1.f - qn) : qn;
                                lq += fabsf(tp - xt) * mt * wq;
                                sTPT[p * 17 + r] = tp;
                            }
                        }
                    }
                }
            }
        }
        __syncthreads();

        // ---- G chunk-0 prefetch (hidden under F) ----
        float4 gpre[5];
        #pragma unroll
        for (int i = 0; i < 5; ++i)
            gpre[i] = gsrc4[tid + i * NTHR];

        // ---- F: ensemble mean, imp out, cc2 ----
        for (int i = tid; i < NC * 16; i += NTHR) {
            int c = i >> 4, r = i & 15;
            float s = 0.f;
            #pragma unroll
            for (int n = 0; n < NE; ++n) s += sTPT[(n * NC + c) * 17 + r];
            float mean = s * (1.0f / (float)NE);
            float xt = sXM[(c * 17 + r) * 2 + 0];
            float mt = sXM[(c * 17 + r) * 2 + 1];
            l4 += fabsf(xt - mean) * mt;
            float cc = mt * xt + (1.f - mt) * mean;
            out_imp[((size_t)(rowBase + r) * NT + t) * NC + c] = cc;
            aCur[c * 16 + r] = cc;
            aCur[(NC + c) * 16 + r] = mt;
        }
        // ---- ens writes (hoisted indices, no divides) ----
        {
            size_t gb = (size_t)rowBase * NE * NT * NC + (size_t)t * NC;
            for (int r = 0; r < RROWS; ++r, gb += (size_t)NE * NT * NC) {
                float2 xm = *reinterpret_cast<const float2*>(&sXM[(cA * 17 + r) * 2]);
                out_ens[gb + offA] = xm.y * xm.x + (1.f - xm.y) * sTPT[pA * 17 + r];
                if (hasB) {
                    float2 xb = *reinterpret_cast<const float2*>(&sXM[(cB * 17 + r) * 2]);
                    out_ens[gb + offB] = xb.y * xb.x + (1.f - xb.y) * sTPT[pB * 17 + r];
                }
            }
        }
        // ---- loss reduce ----
        {
            float v0 = lm, v1 = l1, v2 = l2, v3 = lq, v4 = l4;
            #pragma unroll
            for (int o = 16; o > 0; o >>= 1) {
                v0 += __shfl_down_sync(0xffffffffu, v0, o);
                v1 += __shfl_down_sync(0xffffffffu, v1, o);
                v2 += __shfl_down_sync(0xffffffffu, v2, o);
                v3 += __shfl_down_sync(0xffffffffu, v3, o);
                v4 += __shfl_down_sync(0xffffffffu, v4, o);
            }
            if (lane == 0) {
                sRED[wrp * 5 + 0] = v0; sRED[wrp * 5 + 1] = v1;
                sRED[wrp * 5 + 2] = v2; sRED[wrp * 5 + 3] = v3;
                sRED[wrp * 5 + 4] = v4;
            }
        }
        __syncthreads();
        if (tid == 0) {
            float s0 = 0.f, s1 = 0.f, s2 = 0.f, s3 = 0.f, s4 = 0.f;
            for (int w = 0; w < NTHR / 32; ++w) {
                s0 += sRED[w * 5 + 0]; s1 += sRED[w * 5 + 1];
                s2 += sRED[w * 5 + 2]; s3 += sRED[w * 5 + 3];
                s4 += sRED[w * 5 + 4];
            }
            float* gp = g_blk + ((size_t)blockIdx.x * NT + t) * 5;
            gp[0] = s0; gp[1] = s1; gp[2] = s2; gp[3] = s3; gp[4] = s4;
        }

        // ---- G: LSTM gates GEMM (conflict-free staging both ends) + cell update ----
        {
            u64 acc[4][2];
            #pragma unroll
            for (int j = 0; j < 4; ++j) { acc[j][0] = 0ull; acc[j][1] = 0ull; }
            for (int ch = 0; ch < GCH; ++ch) {
                float* wb = sWB + (ch & 1) * GSTG;
                #pragma unroll
                for (int i = 0; i < 5; ++i)
                    *reinterpret_cast<float4*>(wb + gDst[i]) = gpre[i];
                if (ch + 1 < GCH) {
                    #pragma unroll
                    for (int i = 0; i < 5; ++i)
                        gpre[i] = gsrc4[(ch + 1) * (GRCH / 4) + tid + i * NTHR];
                }
                __syncthreads();
                const float* wrow = wb + uG * 84;
                int kbase = ch * GKC;
                #pragma unroll
                for (int kk0 = 0; kk0 < GKC; kk0 += 4) {
                    float4 w0 = *reinterpret_cast<const float4*>(wrow + 0 * 20 + kk0);
                    float4 w1 = *reinterpret_cast<const float4*>(wrow + 1 * 20 + kk0);
                    float4 w2 = *reinterpret_cast<const float4*>(wrow + 2 * 20 + kk0);
                    float4 w3 = *reinterpret_cast<const float4*>(wrow + 3 * 20 + kk0);
                    #pragma unroll
                    for (int kk = 0; kk < 4; ++kk) {
                        ulonglong2 a2 = *reinterpret_cast<const ulonglong2*>(
                            &aCur[(kbase + kk0 + kk) * 16 + r0g]);
                        u64 b0 = bcast2(getc4(w0, kk));
                        fma2(acc[0][0], a2.x, b0); fma2(acc[0][1], a2.y, b0);
                        u64 b1 = bcast2(getc4(w1, kk));
                        fma2(acc[1][0], a2.x, b1); fma2(acc[1][1], a2.y, b1);
                        u64 b2 = bcast2(getc4(w2, kk));
                        fma2(acc[2][0], a2.x, b2); fma2(acc[2][1], a2.y, b2);
                        u64 b3 = bcast2(getc4(w3, kk));
                        fma2(acc[3][0], a2.x, b3); fma2(acc[3][1], a2.y, b3);
                    }
                }
            }
            // epilogue: cell update
            float bi = sBIA[B_PBG + uG * 4 + 0];
            float bf = sBIA[B_PBG + uG * 4 + 1];
            float bg = sBIA[B_PBG + uG * 4 + 2];
            float bo = sBIA[B_PBG + uG * 4 + 3];
            #pragma unroll
            for (int pp = 0; pp < 2; ++pp) {
                float2 gi2 = unpack2(acc[0][pp]);
                float2 gf2 = unpack2(acc[1][pp]);
                float2 gg2 = unpack2(acc[2][pp]);
                float2 go2 = unpack2(acc[3][pp]);
                #pragma unroll
                for (int rr = 0; rr < 2; ++rr) {
                    int r = r0g + pp * 2 + rr;
                    float gi_ = ((rr == 0) ? gi2.x : gi2.y) + bi;
                    float gf_ = ((rr == 0) ? gf2.x : gf2.y) + bf;
                    float gg_ = ((rr == 0) ? gg2.x : gg2.y) + bg;
                    float go_ = ((rr == 0) ? go2.x : go2.y) + bo;
                    float cn = sigmoidf_(gf_) * sCT[uG * 17 + r]
                             + sigmoidf_(gi_) * ftanh_(gg_);
                    sCT[uG * 17 + r] = cn;
                    aNxt[(72 + uG) * 16 + r] = sigmoidf_(go_) * ftanh_(cn);
                }
            }
        }
        __syncthreads();
        float* tmp = aCur; aCur = aNxt; aNxt = tmp;
    }

    // ---- fused finalize: last block reduces g_blk -> out_loss ----
    __threadfence();
    int* sIsLast = reinterpret_cast<int*>(sRED + 79);
    double* terms = reinterpret_cast<double*>(sm + O_TPT);
    if (tid == 0) {
        int ticket = atomicAdd(&g_done, 1);
        *sIsLast = (ticket == NBLK - 1) ? 1 : 0;
    }
    __syncthreads();
    if (*sIsLast) {
        for (int t = wrp; t < NT; t += 16) {
            double s0 = 0.0, s1 = 0.0, s2 = 0.0, s3 = 0.0, s4 = 0.0;
            for (int b = lane; b < NBLK; b += 32) {
                const float* gp = g_blk + ((size_t)b * NT + t) * 5;
                s0 += (double)gp[0]; s1 += (double)gp[1]; s2 += (double)gp[2];
                s3 += (double)gp[3]; s4 += (double)gp[4];
            }
            #pragma unroll
            for (int o = 16; o > 0; o >>= 1) {
                s0 += __shfl_down_sync(0xffffffffu, s0, o);
                s1 += __shfl_down_sync(0xffffffffu, s1, o);
                s2 += __shfl_down_sync(0xffffffffu, s2, o);
                s3 += __shfl_down_sync(0xffffffffu, s3, o);
                s4 += __shfl_down_sync(0xffffffffu, s4, o);
            }
            if (lane == 0) {
                double pm = s0 + 1e-5;
                terms[t] = (s1 + s2 + s4 + s3 / (double)NE) / pm;
            }
        }
        __syncthreads();
        if (tid == 0) {
            double s = 0.0;
            for (int i = 0; i < NT; ++i) s += terms[i];
            out_loss[0] = (float)(s / (double)NT);
        }
    }
}

extern "C" void kernel_launch(void* const* d_in, const int* in_sizes, int n_in,
                              void* d_out, int out_size)
{
    const float* x      = (const float*)d_in[0];
    const float* mask   = (const float*)d_in[1];
    const float* delta  = (const float*)d_in[2];
    const float* w_dh   = (const float*)d_in[3];
    const float* b_dh   = (const float*)d_in[4];
    const float* w_dx   = (const float*)d_in[5];
    const float* b_dx   = (const float*)d_in[6];
    const float* w_hr   = (const float*)d_in[7];
    const float* b_hr   = (const float*)d_in[8];
    const float* w_fr   = (const float*)d_in[9];
    const float* b_fr   = (const float*)d_in[10];
    const float* w_comb = (const float*)d_in[11];
    const float* b_comb = (const float*)d_in[12];
    const float* w_ih   = (const float*)d_in[13];
    const float* w_hh   = (const float*)d_in[14];
    const float* b_ih   = (const float*)d_in[15];
    const float* b_hh   = (const float*)d_in[16];

    float* out = (float*)d_out;
    float* out_imp = out + 1;
    float* out_ens = out_imp + (size_t)NBATCH * NT * NC;

    const int smem_bytes = SMEM_FLOATS * (int)sizeof(float);
    cudaFuncSetAttribute(brits_main, cudaFuncAttributeMaxDynamicSharedMemorySize,
                         smem_bytes);

    brits_prep<<<256, 256>>>(w_fr, w_comb, w_ih, w_hh, b_ih, b_hh, w_dx);
    brits_main<<<NBLK, NTHR, smem_bytes>>>(
        x, mask, delta, w_dh, b_dh, b_dx, w_hr, b_hr, b_fr, b_comb,
        out, out_imp, out_ens);
}